// round 1
// baseline (speedup 1.0000x reference)
#include <cuda_runtime.h>
#include <math.h>

// x: [B=64, S=4096, N=25, F=3] fp32
// out: [B, S, N, 5] fp32 : {x0, x1, x2, dist(x, x_next), angle(x, x_next)}
// x_next = x at s+1 (same b, n), clamped to itself at s == S-1.

#define B_ 64
#define S_ 4096
#define N_ 25
#define F_ 3

__global__ __launch_bounds__(256) void posenc_kernel(
    const float* __restrict__ x,
    float* __restrict__ out,
    int n_points)
{
    int p = blockIdx.x * blockDim.x + threadIdx.x;
    if (p >= n_points) return;

    // point index p = ((b*S) + s)*N + n ; we only need s to detect the clamp.
    int s = (p / N_) & (S_ - 1);   // (p / 25) % 4096

    const float* __restrict__ a = x + (size_t)p * F_;
    // neighbor: same (b, n), s+1  -> +N_*F_ floats, unless last step.
    const float* __restrict__ b = (s == S_ - 1) ? a : (a + N_ * F_);

    float x0 = a[0], x1 = a[1], x2 = a[2];
    float y0 = b[0], y1 = b[1], y2 = b[2];

    float d0 = y0 - x0, d1 = y1 - x1, d2 = y2 - x2;
    float dist = sqrtf(d0 * d0 + d1 * d1 + d2 * d2);

    float dot = x0 * y0 + x1 * y1 + x2 * y2;
    float la  = sqrtf(x0 * x0 + x1 * x1 + x2 * x2);
    float lb  = sqrtf(y0 * y0 + y1 * y1 + y2 * y2);

    float ang = acosf(dot / (la * lb));
    // jnp.nan_to_num: NaN -> 0 (|ratio| > 1 from rounding, or 0-norm vectors)
    if (isnan(ang)) ang = 0.0f;

    float* __restrict__ o = out + (size_t)p * 5;
    o[0] = x0;
    o[1] = x1;
    o[2] = x2;
    o[3] = dist;
    o[4] = ang;
}

extern "C" void kernel_launch(void* const* d_in, const int* in_sizes, int n_in,
                              void* d_out, int out_size)
{
    const float* x = (const float*)d_in[0];
    float* out = (float*)d_out;

    int n_points = in_sizes[0] / F_;           // B*S*N = 6,553,600
    int threads = 256;
    int blocks = (n_points + threads - 1) / threads;

    posenc_kernel<<<blocks, threads>>>(x, out, n_points);
}